// round 10
// baseline (speedup 1.0000x reference)
#include <cuda_runtime.h>
#include <cstdint>

// Problem constants: N=200000 nodes, D=256 features, G=512 graphs.
#define D 256
#define G 512
#define GPB 16                 // graphs per block-tile in GEMM
#define KPB 16                 // k-values per block-slice in GEMM
#define RPB 128                // rows per block in segsum

__device__ int   g_layout;         // 0 = int32 indices, 1 = int64 indices
__device__ float g_sum[G * D];     // pooled features
__device__ float g_acc[G * D];     // bias-seeded split-K accumulator -> sum@W + b

__device__ __forceinline__ int load_idx(const int* __restrict__ raw, int i, int layout)
{
    return layout ? raw[2 * i] : raw[i];
}

// ---------------------------------------------------------------------------
// Kernel 1: zero g_sum, seed g_acc with the bias (so the split-K GEMM's
// atomic adds finish g_acc = sum @ W + b with no extra pass), and detect
// index storage layout from the LAST 256 int32 words (batch_idx sorted:
// int32 => odd words nonzero; int64 (<2^32) => odd zero, even nonzero;
// all-zero => either path correct).
// ---------------------------------------------------------------------------
__global__ void k_init(const int* __restrict__ raw, const float* __restrict__ b, int n)
{
    int i = blockIdx.x * blockDim.x + threadIdx.x;
    g_sum[i] = 0.0f;
    g_acc[i] = b[i & (D - 1)];

    if (blockIdx.x == 0) {
        int w = n - 256 + threadIdx.x;
        int odd_nz = 0, even_nz = 0;
        if (w >= 0) {
            int v = raw[w];
            if (v != 0) {
                if (w & 1) odd_nz = 1; else even_nz = 1;
            }
        }
        int o = __syncthreads_or(odd_nz);
        int e = __syncthreads_or(even_nz);
        if (threadIdx.x == 0)
            g_layout = o ? 0 : (e ? 1 : 0);
    }
}

// ---------------------------------------------------------------------------
// Kernel 2: segment sum, MLP-batched (measured ~32us = BW floor).
// ---------------------------------------------------------------------------
__global__ void __launch_bounds__(256) k_segsum(const float* __restrict__ h,
                                                const int* __restrict__ raw, int n)
{
    __shared__ int sidx[RPB];
    int layout = g_layout;
    int r0 = blockIdx.x * RPB;
    if (threadIdx.x < RPB) {
        int r = r0 + threadIdx.x;
        sidx[threadIdx.x] = (r < n) ? load_idx(raw, r, layout) : -1;
    }
    __syncthreads();

    int tx = threadIdx.x & 63;
    int ty = threadIdx.x >> 6;

    float4 acc = make_float4(0.f, 0.f, 0.f, 0.f);
    int cur = -1;

#pragma unroll
    for (int base = 0; base < RPB; base += 32) {
        float4 v[8];
#pragma unroll
        for (int j = 0; j < 8; j++) {
            int row = r0 + base + ty + j * 4;
            if (row < n)
                v[j] = *reinterpret_cast<const float4*>(h + (size_t)row * D + tx * 4);
            else
                v[j] = make_float4(0.f, 0.f, 0.f, 0.f);
        }
#pragma unroll
        for (int j = 0; j < 8; j++) {
            int rr = base + ty + j * 4;
            if (r0 + rr >= n) break;
            int seg = sidx[rr];
            if (seg != cur) {
                if (cur >= 0) {
                    float* dst = &g_sum[cur * D + tx * 4];
                    atomicAdd(dst + 0, acc.x);
                    atomicAdd(dst + 1, acc.y);
                    atomicAdd(dst + 2, acc.z);
                    atomicAdd(dst + 3, acc.w);
                }
                acc = make_float4(0.f, 0.f, 0.f, 0.f);
                cur = seg;
            }
            acc.x += v[j].x; acc.y += v[j].y; acc.z += v[j].z; acc.w += v[j].w;
        }
    }
    if (cur >= 0) {
        float* dst = &g_sum[cur * D + tx * 4];
        atomicAdd(dst + 0, acc.x);
        atomicAdd(dst + 1, acc.y);
        atomicAdd(dst + 2, acc.z);
        atomicAdd(dst + 3, acc.w);
    }
}

// ---------------------------------------------------------------------------
// Kernel 3: split-K GEMM, exact R7 form (measured 7.9us). grid (32,16) =
// 512 blocks; accumulates on top of the bias-seeded g_acc.
// ---------------------------------------------------------------------------
__global__ void __launch_bounds__(256) k_gemm_splitk(const float* __restrict__ W)
{
    __shared__ float s[GPB][KPB];
    int g0 = blockIdx.x * GPB;
    int k0 = blockIdx.y * KPB;
    int t  = threadIdx.x;

    float w[KPB];
#pragma unroll
    for (int kk = 0; kk < KPB; kk++)
        w[kk] = __ldg(&W[(k0 + kk) * D + t]);

    {
        int r  = t >> 4;
        int kk = t & 15;
        s[r][kk] = g_sum[(g0 + r) * D + (k0 + kk)];
    }
    __syncthreads();

    float acc[GPB];
#pragma unroll
    for (int r = 0; r < GPB; r++) acc[r] = 0.0f;

#pragma unroll
    for (int kk = 0; kk < KPB; kk++) {
#pragma unroll
        for (int r = 0; r < GPB; r++)
            acc[r] = fmaf(s[r][kk], w[kk], acc[r]);
    }

#pragma unroll
    for (int r = 0; r < GPB; r++)
        atomicAdd(&g_acc[(g0 + r) * D + t], acc[r]);
}

// ---------------------------------------------------------------------------
// Kernel 4: out = relu(g_acc[seg]) + h. Bias already inside g_acc, so no b
// loads. One thread per 4 float4 quads (16 threads/row): per-quad L1
// wavefronts drop 4.5 -> 3.25, front-batched MLP=8. Reverse row order
// harvests the L2 tail left by k_segsum; misses evict-first.
// ---------------------------------------------------------------------------
__global__ void k_out(const float* __restrict__ h, const int* __restrict__ raw,
                      float* __restrict__ out, int n)
{
    int layout = g_layout;
    int gt = blockIdx.x * blockDim.x + threadIdx.x;   // one thread per 4 quads
    int ridx = gt >> 4;
    if (ridx >= n) return;
    int i = n - 1 - ridx;     // reverse row order
    int q = (gt & 15) * 4;    // first of four column quads
    int seg = load_idx(raw, i, layout);

    const float4* hp = reinterpret_cast<const float4*>(h + (size_t)i * D) + q;
    const float4* vp = reinterpret_cast<const float4*>(g_acc + seg * D) + q;

    float4 a0 = __ldcs(hp + 0);
    float4 a1 = __ldcs(hp + 1);
    float4 a2 = __ldcs(hp + 2);
    float4 a3 = __ldcs(hp + 3);
    float4 v0 = vp[0];
    float4 v1 = vp[1];
    float4 v2 = vp[2];
    float4 v3 = vp[3];

    float4 r0, r1, r2, r3;
    r0.x = fmaxf(v0.x, 0.0f) + a0.x;  r0.y = fmaxf(v0.y, 0.0f) + a0.y;
    r0.z = fmaxf(v0.z, 0.0f) + a0.z;  r0.w = fmaxf(v0.w, 0.0f) + a0.w;
    r1.x = fmaxf(v1.x, 0.0f) + a1.x;  r1.y = fmaxf(v1.y, 0.0f) + a1.y;
    r1.z = fmaxf(v1.z, 0.0f) + a1.z;  r1.w = fmaxf(v1.w, 0.0f) + a1.w;
    r2.x = fmaxf(v2.x, 0.0f) + a2.x;  r2.y = fmaxf(v2.y, 0.0f) + a2.y;
    r2.z = fmaxf(v2.z, 0.0f) + a2.z;  r2.w = fmaxf(v2.w, 0.0f) + a2.w;
    r3.x = fmaxf(v3.x, 0.0f) + a3.x;  r3.y = fmaxf(v3.y, 0.0f) + a3.y;
    r3.z = fmaxf(v3.z, 0.0f) + a3.z;  r3.w = fmaxf(v3.w, 0.0f) + a3.w;

    float4* op = reinterpret_cast<float4*>(out + (size_t)i * D) + q;
    __stcs(op + 0, r0);
    __stcs(op + 1, r1);
    __stcs(op + 2, r2);
    __stcs(op + 3, r3);
}

extern "C" void kernel_launch(void* const* d_in, const int* in_sizes, int n_in,
                              void* d_out, int out_size)
{
    const float* h   = (const float*)d_in[0];
    const int*   raw = (const int*)  d_in[1];
    const float* W   = (const float*)d_in[2];
    const float* b   = (const float*)d_in[3];
    float* out = (float*)d_out;

    const int n  = in_sizes[1];
    const int nbs = (n + RPB - 1) / RPB;

    k_init  <<<G * D / 256, 256>>>(raw, b, n);
    k_segsum<<<nbs, 256>>>(h, raw, n);
    k_gemm_splitk<<<dim3(G / GPB, D / KPB), 256>>>(W);
    {
        long long tt = (long long)n * 16;   // one thread per 4 float4
        int blocks = (int)((tt + 255) / 256);
        k_out<<<blocks, 256>>>(h, raw, out, n);
    }
}

// round 11
// speedup vs baseline: 1.2246x; 1.2246x over previous
#include <cuda_runtime.h>
#include <cstdint>

// Problem constants: N=200000 nodes, D=256 features, G=512 graphs.
#define D 256
#define G 512
#define GPB 16                 // graphs per block-tile in GEMM
#define KPB 16                 // k-values per block-slice in GEMM
#define RPB 128                // rows per block in segsum

__device__ int   g_layout;         // 0 = int32 indices, 1 = int64 indices
__device__ float g_sum[G * D];     // pooled features
__device__ float g_acc[G * D];     // bias-seeded split-K accumulator -> sum@W + b

__device__ __forceinline__ int load_idx(const int* __restrict__ raw, int i, int layout)
{
    return layout ? raw[2 * i] : raw[i];
}

// ---------------------------------------------------------------------------
// Kernel 1: zero g_sum, seed g_acc with the bias (so the split-K GEMM's
// atomic adds finish g_acc = sum @ W + b with no extra pass), and detect
// index storage layout from the LAST 256 int32 words (batch_idx sorted:
// int32 => odd words nonzero; int64 (<2^32) => odd zero, even nonzero;
// all-zero => either path correct).
// ---------------------------------------------------------------------------
__global__ void k_init(const int* __restrict__ raw, const float* __restrict__ b, int n)
{
    int i = blockIdx.x * blockDim.x + threadIdx.x;
    g_sum[i] = 0.0f;
    g_acc[i] = b[i & (D - 1)];

    if (blockIdx.x == 0) {
        int w = n - 256 + threadIdx.x;
        int odd_nz = 0, even_nz = 0;
        if (w >= 0) {
            int v = raw[w];
            if (v != 0) {
                if (w & 1) odd_nz = 1; else even_nz = 1;
            }
        }
        int o = __syncthreads_or(odd_nz);
        int e = __syncthreads_or(even_nz);
        if (threadIdx.x == 0)
            g_layout = o ? 0 : (e ? 1 : 0);
    }
}

// ---------------------------------------------------------------------------
// Kernel 2: segment sum, MLP-batched (measured ~32us = BW floor).
// Block owns RPB=128 contiguous rows; 64 column-quads x 4 row-stripes.
// Chunks of 8 rows: batch the 8 independent float4 loads (MLP=8), then run
// segment logic on registers; atomic flush only on boundaries.
// ---------------------------------------------------------------------------
__global__ void __launch_bounds__(256) k_segsum(const float* __restrict__ h,
                                                const int* __restrict__ raw, int n)
{
    __shared__ int sidx[RPB];
    int layout = g_layout;
    int r0 = blockIdx.x * RPB;
    if (threadIdx.x < RPB) {
        int r = r0 + threadIdx.x;
        sidx[threadIdx.x] = (r < n) ? load_idx(raw, r, layout) : -1;
    }
    __syncthreads();

    int tx = threadIdx.x & 63;
    int ty = threadIdx.x >> 6;

    float4 acc = make_float4(0.f, 0.f, 0.f, 0.f);
    int cur = -1;

#pragma unroll
    for (int base = 0; base < RPB; base += 32) {
        float4 v[8];
#pragma unroll
        for (int j = 0; j < 8; j++) {
            int row = r0 + base + ty + j * 4;
            if (row < n)
                v[j] = *reinterpret_cast<const float4*>(h + (size_t)row * D + tx * 4);
            else
                v[j] = make_float4(0.f, 0.f, 0.f, 0.f);
        }
#pragma unroll
        for (int j = 0; j < 8; j++) {
            int rr = base + ty + j * 4;
            if (r0 + rr >= n) break;
            int seg = sidx[rr];
            if (seg != cur) {
                if (cur >= 0) {
                    float* dst = &g_sum[cur * D + tx * 4];
                    atomicAdd(dst + 0, acc.x);
                    atomicAdd(dst + 1, acc.y);
                    atomicAdd(dst + 2, acc.z);
                    atomicAdd(dst + 3, acc.w);
                }
                acc = make_float4(0.f, 0.f, 0.f, 0.f);
                cur = seg;
            }
            acc.x += v[j].x; acc.y += v[j].y; acc.z += v[j].z; acc.w += v[j].w;
        }
    }
    if (cur >= 0) {
        float* dst = &g_sum[cur * D + tx * 4];
        atomicAdd(dst + 0, acc.x);
        atomicAdd(dst + 1, acc.y);
        atomicAdd(dst + 2, acc.z);
        atomicAdd(dst + 3, acc.w);
    }
}

// ---------------------------------------------------------------------------
// Kernel 3: split-K GEMM, exact R7 form (measured 7.9us). grid (32,16) =
// 512 blocks; accumulates on top of the bias-seeded g_acc.
// ---------------------------------------------------------------------------
__global__ void __launch_bounds__(256) k_gemm_splitk(const float* __restrict__ W)
{
    __shared__ float s[GPB][KPB];
    int g0 = blockIdx.x * GPB;
    int k0 = blockIdx.y * KPB;
    int t  = threadIdx.x;

    float w[KPB];
#pragma unroll
    for (int kk = 0; kk < KPB; kk++)
        w[kk] = __ldg(&W[(k0 + kk) * D + t]);

    {
        int r  = t >> 4;
        int kk = t & 15;
        s[r][kk] = g_sum[(g0 + r) * D + (k0 + kk)];
    }
    __syncthreads();

    float acc[GPB];
#pragma unroll
    for (int r = 0; r < GPB; r++) acc[r] = 0.0f;

#pragma unroll
    for (int kk = 0; kk < KPB; kk++) {
#pragma unroll
        for (int r = 0; r < GPB; r++)
            acc[r] = fmaf(s[r][kk], w[kk], acc[r]);
    }

#pragma unroll
    for (int r = 0; r < GPB; r++)
        atomicAdd(&g_acc[(g0 + r) * D + t], acc[r]);
}

// ---------------------------------------------------------------------------
// Kernel 4: out = relu(g_acc[seg]) + h — R6's lean 2-quad form (measured
// 62.9us), now with bias pre-folded into g_acc so no b loads. One thread
// per 2 quads keeps live state within 32 regs (loads stay batched; the
// 4-quad variant serialized and regressed). Reverse row order harvests the
// L2 tail left by k_segsum; misses evict-first.
// ---------------------------------------------------------------------------
__global__ void k_out(const float* __restrict__ h, const int* __restrict__ raw,
                      float* __restrict__ out, int n)
{
    int layout = g_layout;
    int gt = blockIdx.x * blockDim.x + threadIdx.x;   // one thread per 2 quads
    int ridx = gt >> 5;
    if (ridx >= n) return;
    int i = n - 1 - ridx;     // reverse row order
    int q = (gt & 31) * 2;
    int seg = load_idx(raw, i, layout);

    const float4* hp = reinterpret_cast<const float4*>(h + (size_t)i * D) + q;
    const float4 a0 = __ldcs(hp);
    const float4 a1 = __ldcs(hp + 1);
    const float4* vp = reinterpret_cast<const float4*>(g_acc + seg * D) + q;
    const float4 v0 = vp[0];
    const float4 v1 = vp[1];

    float4 r0, r1;
    r0.x = fmaxf(v0.x, 0.0f) + a0.x;  r0.y = fmaxf(v0.y, 0.0f) + a0.y;
    r0.z = fmaxf(v0.z, 0.0f) + a0.z;  r0.w = fmaxf(v0.w, 0.0f) + a0.w;
    r1.x = fmaxf(v1.x, 0.0f) + a1.x;  r1.y = fmaxf(v1.y, 0.0f) + a1.y;
    r1.z = fmaxf(v1.z, 0.0f) + a1.z;  r1.w = fmaxf(v1.w, 0.0f) + a1.w;

    float4* op = reinterpret_cast<float4*>(out + (size_t)i * D) + q;
    __stcs(op, r0);
    __stcs(op + 1, r1);
}

extern "C" void kernel_launch(void* const* d_in, const int* in_sizes, int n_in,
                              void* d_out, int out_size)
{
    const float* h   = (const float*)d_in[0];
    const int*   raw = (const int*)  d_in[1];
    const float* W   = (const float*)d_in[2];
    const float* b   = (const float*)d_in[3];
    float* out = (float*)d_out;

    const int n  = in_sizes[1];
    const int nbs = (n + RPB - 1) / RPB;

    k_init  <<<G * D / 256, 256>>>(raw, b, n);
    k_segsum<<<nbs, 256>>>(h, raw, n);
    k_gemm_splitk<<<dim3(G / GPB, D / KPB), 256>>>(W);
    {
        long long tt = (long long)n * 32;   // one thread per 2 float4
        int blocks = (int)((tt + 255) / 256);
        k_out<<<blocks, 256>>>(h, raw, out, n);
    }
}